// round 1
// baseline (speedup 1.0000x reference)
#include <cuda_runtime.h>
#include <math.h>

#define BATCH   2
#define SEQ     1024
#define DMODEL  1024
#define DIN     2048
#define DSTATE  16
#define DTRANK  64
#define XDBL    96          // dt_rank + 2*d_state
#define NCHUNK  16
#define TCHUNK  64          // SEQ / NCHUNK

// ---------------- scratch (static device globals; no allocs) ----------------
__device__ float g_xz   [BATCH*SEQ*2*DIN];      // 32 MB  (x | z)
__device__ float g_u    [BATCH*SEQ*DIN];        // 16 MB  silu(conv(x))
__device__ float g_xdbl [BATCH*SEQ*XDBL];       // dt_low | B | C
__device__ float g_delta[BATCH*SEQ*DIN];        // softplus(dt)
__device__ float g_yg   [BATCH*SEQ*DIN];        // gated scan output
__device__ float g_P    [BATCH*NCHUNK*DIN*DSTATE];
__device__ float g_q    [BATCH*NCHUNK*DIN*DSTATE];
__device__ float g_hs   [BATCH*NCHUNK*DIN*DSTATE];

// ---------------- generic NT GEMM: C[M,N] = A[M,K] * B[N,K]^T ---------------
// act==1: C = softplus(acc + bias[n])
#define BM 64
#define BN 64
#define BK 16
#define SPITCH 68   // 68 floats -> 272B row stride, 16B aligned

__global__ __launch_bounds__(256) void gemm_nt(
    const float* __restrict__ A, int lda,
    const float* __restrict__ B, int ldb,
    float* __restrict__ C, int ldc,
    int M, int N, int K,
    const float* __restrict__ bias, int act)
{
    __shared__ float As[BK][SPITCH];
    __shared__ float Bs[BK][SPITCH];

    int tid = threadIdx.x;
    int bm = blockIdx.y * BM;
    int bn = blockIdx.x * BN;

    int row = tid >> 2;            // 0..63
    int k4  = (tid & 3) * 4;       // 0,4,8,12
    int ty  = tid >> 4;            // 0..15
    int tx  = tid & 15;            // 0..15

    float acc[4][4] = {};

    const float* Aptr = A + (bm + row) * lda + k4;   // M always %64==0 here
    const float* Bptr = B + (bn + row) * ldb + k4;
    bool bvalid = (bn + row) < N;

    for (int k0 = 0; k0 < K; k0 += BK) {
        float4 av = *(const float4*)(Aptr + k0);
        float4 bv = make_float4(0.f, 0.f, 0.f, 0.f);
        if (bvalid) bv = *(const float4*)(Bptr + k0);

        As[k4+0][row] = av.x; As[k4+1][row] = av.y;
        As[k4+2][row] = av.z; As[k4+3][row] = av.w;
        Bs[k4+0][row] = bv.x; Bs[k4+1][row] = bv.y;
        Bs[k4+2][row] = bv.z; Bs[k4+3][row] = bv.w;
        __syncthreads();

        #pragma unroll
        for (int k = 0; k < BK; k++) {
            float4 a = *(const float4*)&As[k][ty*4];
            float4 b = *(const float4*)&Bs[k][tx*4];
            float af[4] = {a.x, a.y, a.z, a.w};
            float bf[4] = {b.x, b.y, b.z, b.w};
            #pragma unroll
            for (int i = 0; i < 4; i++)
                #pragma unroll
                for (int j = 0; j < 4; j++)
                    acc[i][j] = fmaf(af[i], bf[j], acc[i][j]);
        }
        __syncthreads();
    }

    #pragma unroll
    for (int i = 0; i < 4; i++) {
        int m = bm + ty*4 + i;
        #pragma unroll
        for (int j = 0; j < 4; j++) {
            int n = bn + tx*4 + j;
            if (n < N) {
                float v = acc[i][j];
                if (act == 1) {
                    v += bias[n];
                    v = (v > 20.0f) ? v : log1pf(__expf(v));
                }
                C[m * ldc + n] = v;
            }
        }
    }
}

// ---------------- causal depthwise conv (width 4) + SiLU --------------------
__global__ __launch_bounds__(256) void conv_silu(
    const float* __restrict__ cw,   // [DIN][4]
    const float* __restrict__ cb)   // [DIN]
{
    int idx = blockIdx.x * 256 + threadIdx.x;      // over BATCH*SEQ*(DIN/4)
    int d4 = idx & (DIN/4 - 1);
    int t  = (idx >> 9) & (SEQ - 1);
    int b  = idx >> 19;
    int d  = d4 * 4;

    // weights for 4 consecutive channels: wf[ch][tap]
    float wf[4][4];
    #pragma unroll
    for (int ch = 0; ch < 4; ch++) {
        float4 w = ((const float4*)cw)[d + ch];
        wf[ch][0] = w.x; wf[ch][1] = w.y; wf[ch][2] = w.z; wf[ch][3] = w.w;
    }
    float4 bias = ((const float4*)cb)[d4];
    float acc[4] = {bias.x, bias.y, bias.z, bias.w};

    #pragma unroll
    for (int j = 0; j < 4; j++) {
        int tt = t - 3 + j;
        if (tt >= 0) {
            const float4 xv = *(const float4*)&g_xz[((b*SEQ + tt) * (2*DIN)) + d];
            acc[0] = fmaf(xv.x, wf[0][j], acc[0]);
            acc[1] = fmaf(xv.y, wf[1][j], acc[1]);
            acc[2] = fmaf(xv.z, wf[2][j], acc[2]);
            acc[3] = fmaf(xv.w, wf[3][j], acc[3]);
        }
    }
    float4 out;
    out.x = acc[0] / (1.f + __expf(-acc[0]));
    out.y = acc[1] / (1.f + __expf(-acc[1]));
    out.z = acc[2] / (1.f + __expf(-acc[2]));
    out.w = acc[3] / (1.f + __expf(-acc[3]));
    *(float4*)&g_u[(b*SEQ + t) * DIN + d] = out;
}

// ---------------- selective scan: phase A (per-chunk affine summary) --------
__global__ __launch_bounds__(256) void scan_partA(const float* __restrict__ Alog)
{
    int d = blockIdx.x * 256 + threadIdx.x;   // 0..2047
    int c = blockIdx.y;                       // chunk
    int b = blockIdx.z;

    float Arow[DSTATE];
    #pragma unroll
    for (int n = 0; n < DSTATE; n++) Arow[n] = -__expf(Alog[d*DSTATE + n]);

    float h[DSTATE], p[DSTATE];
    #pragma unroll
    for (int n = 0; n < DSTATE; n++) { h[n] = 0.f; p[n] = 1.f; }

    for (int i = 0; i < TCHUNK; i++) {
        int t = c * TCHUNK + i;
        int off = (b*SEQ + t) * DIN + d;
        float delta = g_delta[off];
        float u     = g_u[off];
        float du    = delta * u;
        const float4* Bp = (const float4*)(g_xdbl + (b*SEQ + t)*XDBL + DTRANK);
        float4 b0 = Bp[0], b1 = Bp[1], b2 = Bp[2], b3 = Bp[3];
        float Bv[DSTATE] = {b0.x,b0.y,b0.z,b0.w, b1.x,b1.y,b1.z,b1.w,
                            b2.x,b2.y,b2.z,b2.w, b3.x,b3.y,b3.z,b3.w};
        #pragma unroll
        for (int n = 0; n < DSTATE; n++) {
            float dA = __expf(delta * Arow[n]);
            p[n] *= dA;
            h[n] = fmaf(dA, h[n], du * Bv[n]);
        }
    }
    int o = ((b*NCHUNK + c) * DIN + d) * DSTATE;
    #pragma unroll
    for (int j = 0; j < 4; j++) {
        *(float4*)&g_P[o + j*4] = make_float4(p[j*4+0], p[j*4+1], p[j*4+2], p[j*4+3]);
        *(float4*)&g_q[o + j*4] = make_float4(h[j*4+0], h[j*4+1], h[j*4+2], h[j*4+3]);
    }
}

// ---------------- phase B: 16-step prefix over chunks per (b,d,n) -----------
__global__ __launch_bounds__(256) void scan_partB()
{
    int idx = blockIdx.x * 256 + threadIdx.x;    // BATCH*DIN*DSTATE = 65536
    int b = idx >> 15;
    int rest = idx & 32767;
    float h = 0.f;
    for (int c = 0; c < NCHUNK; c++) {
        int o = (b*NCHUNK + c) * (DIN*DSTATE) + rest;
        g_hs[o] = h;                  // exclusive prefix: state entering chunk c
        h = fmaf(g_P[o], h, g_q[o]);
    }
}

// ---------------- phase C: re-scan with correct h0, fuse y, skip, gate ------
__global__ __launch_bounds__(256) void scan_partC(
    const float* __restrict__ Alog, const float* __restrict__ Dv)
{
    int d = blockIdx.x * 256 + threadIdx.x;
    int c = blockIdx.y;
    int b = blockIdx.z;

    float Arow[DSTATE];
    #pragma unroll
    for (int n = 0; n < DSTATE; n++) Arow[n] = -__expf(Alog[d*DSTATE + n]);

    float h[DSTATE];
    {
        int o = ((b*NCHUNK + c) * DIN + d) * DSTATE;
        #pragma unroll
        for (int j = 0; j < 4; j++) {
            float4 v = *(const float4*)&g_hs[o + j*4];
            h[j*4+0] = v.x; h[j*4+1] = v.y; h[j*4+2] = v.z; h[j*4+3] = v.w;
        }
    }
    float Dd = Dv[d];

    for (int i = 0; i < TCHUNK; i++) {
        int t = c * TCHUNK + i;
        int off = (b*SEQ + t) * DIN + d;
        float delta = g_delta[off];
        float u     = g_u[off];
        float du    = delta * u;
        const float4* Bp = (const float4*)(g_xdbl + (b*SEQ + t)*XDBL + DTRANK);
        float4 b0 = Bp[0], b1 = Bp[1], b2 = Bp[2], b3 = Bp[3];
        float Bv[DSTATE] = {b0.x,b0.y,b0.z,b0.w, b1.x,b1.y,b1.z,b1.w,
                            b2.x,b2.y,b2.z,b2.w, b3.x,b3.y,b3.z,b3.w};
        const float4* Cp = (const float4*)(g_xdbl + (b*SEQ + t)*XDBL + DTRANK + DSTATE);
        float4 c0 = Cp[0], c1 = Cp[1], c2 = Cp[2], c3 = Cp[3];
        float Cv[DSTATE] = {c0.x,c0.y,c0.z,c0.w, c1.x,c1.y,c1.z,c1.w,
                            c2.x,c2.y,c2.z,c2.w, c3.x,c3.y,c3.z,c3.w};
        float y = 0.f;
        #pragma unroll
        for (int n = 0; n < DSTATE; n++) {
            float dA = __expf(delta * Arow[n]);
            h[n] = fmaf(dA, h[n], du * Bv[n]);
            y = fmaf(h[n], Cv[n], y);
        }
        float z = g_xz[(b*SEQ + t) * (2*DIN) + DIN + d];
        float gate = z / (1.f + __expf(-z));
        g_yg[off] = (y + u * Dd) * gate;
    }
}

// ---------------------------- launch -----------------------------------------
extern "C" void kernel_launch(void* const* d_in, const int* in_sizes, int n_in,
                              void* d_out, int out_size)
{
    const float* hs     = (const float*)d_in[0];
    const float* w_in   = (const float*)d_in[1];
    const float* conv_w = (const float*)d_in[2];
    const float* conv_b = (const float*)d_in[3];
    const float* w_x    = (const float*)d_in[4];
    const float* w_dt   = (const float*)d_in[5];
    const float* b_dt   = (const float*)d_in[6];
    const float* A_log  = (const float*)d_in[7];
    const float* Dv     = (const float*)d_in[8];
    const float* w_out  = (const float*)d_in[9];
    float* out = (float*)d_out;

    float *xz, *u, *xdbl, *delta, *yg;
    cudaGetSymbolAddress((void**)&xz,    g_xz);
    cudaGetSymbolAddress((void**)&u,     g_u);
    cudaGetSymbolAddress((void**)&xdbl,  g_xdbl);
    cudaGetSymbolAddress((void**)&delta, g_delta);
    cudaGetSymbolAddress((void**)&yg,    g_yg);

    const int M = BATCH * SEQ;   // 2048

    // 1) xz = hs @ in_proj_w^T        [2048, 4096]
    {
        dim3 grid((2*DIN + BN - 1)/BN, M/BM);
        gemm_nt<<<grid, 256>>>(hs, DMODEL, w_in, DMODEL, xz, 2*DIN,
                               M, 2*DIN, DMODEL, nullptr, 0);
    }
    // 2) u = silu(causal depthwise conv(x) + b)
    conv_silu<<<(BATCH*SEQ*(DIN/4))/256, 256>>>(conv_w, conv_b);

    // 3) x_dbl = u @ x_proj_w^T       [2048, 96]
    {
        dim3 grid((XDBL + BN - 1)/BN, M/BM);
        gemm_nt<<<grid, 256>>>(u, DIN, w_x, DIN, xdbl, XDBL,
                               M, XDBL, DIN, nullptr, 0);
    }
    // 4) delta = softplus(dt_low @ dt_proj_w^T + b)   [2048, 2048]
    {
        dim3 grid((DIN + BN - 1)/BN, M/BM);
        gemm_nt<<<grid, 256>>>(xdbl, XDBL, w_dt, DTRANK, delta, DIN,
                               M, DIN, DTRANK, b_dt, 1);
    }
    // 5) selective scan (chunked, exact)
    {
        dim3 gridA(DIN/256, NCHUNK, BATCH);
        scan_partA<<<gridA, 256>>>(A_log);
        scan_partB<<<(BATCH*DIN*DSTATE)/256, 256>>>();
        scan_partC<<<gridA, 256>>>(A_log, Dv);
    }
    // 6) out = yg @ out_proj_w^T      [2048, 1024]
    {
        dim3 grid((DMODEL + BN - 1)/BN, M/BM);
        gemm_nt<<<grid, 256>>>(yg, DIN, w_out, DIN, out, DMODEL,
                               M, DMODEL, DIN, nullptr, 0);
    }
}

// round 4
// speedup vs baseline: 2.3032x; 2.3032x over previous
#include <cuda_runtime.h>
#include <math.h>
#include <stdint.h>

#define BATCH   2
#define SEQ     1024
#define DMODEL  1024
#define DIN     2048
#define DSTATE  16
#define DTRANK  64
#define XDBL    96
#define NCHUNK  16
#define TCHUNK  64

// ---------------- scratch (static device globals; no allocs) ----------------
__device__ float g_xz   [BATCH*SEQ*2*DIN];
__device__ float g_u    [BATCH*SEQ*DIN];
__device__ float g_xdbl [BATCH*SEQ*XDBL];
__device__ float g_delta[BATCH*SEQ*DIN];
__device__ float g_yg   [BATCH*SEQ*DIN];
__device__ float g_P    [BATCH*NCHUNK*DIN*DSTATE];
__device__ float g_q    [BATCH*NCHUNK*DIN*DSTATE];
__device__ float g_hs   [BATCH*NCHUNK*DIN*DSTATE];

// ---------------------------- helpers ---------------------------------------
__device__ __forceinline__ uint32_t f2tf(float f) {
    uint32_t o;
    asm("cvt.rna.tf32.f32 %0, %1;" : "=r"(o) : "f"(f));
    return o;
}
__device__ __forceinline__ void mma_tf32(float& c0, float& c1, float& c2, float& c3,
                                         uint32_t a0, uint32_t a1, uint32_t a2, uint32_t a3,
                                         uint32_t b0, uint32_t b1) {
    asm volatile("mma.sync.aligned.m16n8k8.row.col.f32.tf32.tf32.f32 "
                 "{%0,%1,%2,%3}, {%4,%5,%6,%7}, {%8,%9}, {%0,%1,%2,%3};"
                 : "+f"(c0), "+f"(c1), "+f"(c2), "+f"(c3)
                 : "r"(a0), "r"(a1), "r"(a2), "r"(a3), "r"(b0), "r"(b1));
}

// ========== tf32 mma.sync GEMM: C[M,N] = A[M,K] * B[N,K]^T ==================
// Block tile 128x128x32, 256 threads = 8 warps (2 m x 4 n), warp tile 64x32.
// Double-buffered smem, LDG->cvt.rna.tf32->STS staging.
// ACT==1: C = softplus(acc + bias[n])
#define GP 36            // smem row pitch in floats (padded, 16B aligned)
#define STAGE_F (128*GP) // floats per (A or B) stage
#define MMA_SMEM_BYTES (4*STAGE_F*4)

template<int N, int K, int ACT>
__global__ __launch_bounds__(256, 1) void gemm_mma(
    const float* __restrict__ A, const float* __restrict__ B,
    float* __restrict__ C, const float* __restrict__ bias)
{
    extern __shared__ float smf[];
    float* As = smf;               // [2][STAGE_F]
    float* Bs = smf + 2*STAGE_F;   // [2][STAGE_F]

    const int t   = threadIdx.x;
    const int w   = t >> 5;
    const int l   = t & 31;
    const int g   = l >> 2;        // group id 0..7
    const int tig = l & 3;         // thread in group 0..3
    const int wm  = (w >> 2) * 64; // warp m offset within block
    const int wn  = (w & 3) * 32;  // warp n offset within block

    const int bm = blockIdx.y * 128;
    const int bn = blockIdx.x * 128;

    const float* Ag = A + (size_t)bm * K;
    const float* Bg = B + (size_t)bn * K;

    // per-thread load coords (same for every k-tile)
    int lr[4], lk[4];
    #pragma unroll
    for (int j = 0; j < 4; j++) {
        int u = j * 256 + t;
        lr[j] = u >> 3;        // row 0..127
        lk[j] = (u & 7) * 4;   // k-offset within 32: 0,4,...,28
    }

    float acc[4][4][4];  // [mtile][ntile][frag]
    #pragma unroll
    for (int i = 0; i < 4; i++)
        #pragma unroll
        for (int j = 0; j < 4; j++)
            #pragma unroll
            for (int q = 0; q < 4; q++) acc[i][j][q] = 0.f;

    constexpr int KT = K / 32;

    // ---- prologue: fill stage 0 ----
    {
        #pragma unroll
        for (int j = 0; j < 4; j++) {
            float4 va = *(const float4*)(Ag + (size_t)lr[j]*K + lk[j]);
            uint32_t* d = (uint32_t*)&As[lr[j]*GP + lk[j]];
            d[0] = f2tf(va.x); d[1] = f2tf(va.y); d[2] = f2tf(va.z); d[3] = f2tf(va.w);
            float4 vb = make_float4(0.f,0.f,0.f,0.f);
            if (bn + lr[j] < N) vb = *(const float4*)(Bg + (size_t)lr[j]*K + lk[j]);
            uint32_t* e = (uint32_t*)&Bs[lr[j]*GP + lk[j]];
            e[0] = f2tf(vb.x); e[1] = f2tf(vb.y); e[2] = f2tf(vb.z); e[3] = f2tf(vb.w);
        }
    }
    __syncthreads();

    #pragma unroll 1
    for (int kt = 0; kt < KT; kt++) {
        const int s = kt & 1;
        float4 pa[4], pb[4];
        const bool more = (kt + 1 < KT);
        if (more) {
            const int k0 = (kt + 1) * 32;
            #pragma unroll
            for (int j = 0; j < 4; j++) {
                pa[j] = *(const float4*)(Ag + (size_t)lr[j]*K + k0 + lk[j]);
                pb[j] = make_float4(0.f,0.f,0.f,0.f);
                if (bn + lr[j] < N)
                    pb[j] = *(const float4*)(Bg + (size_t)lr[j]*K + k0 + lk[j]);
            }
        }

        // ---- compute on stage s ----
        const float* Ab = As + s * STAGE_F;
        const float* Bb = Bs + s * STAGE_F;
        #pragma unroll
        for (int q = 0; q < 4; q++) {
            uint32_t af[4][4], bf[4][2];
            #pragma unroll
            for (int i = 0; i < 4; i++) {
                int r0 = wm + i*16 + g;
                af[i][0] = __float_as_uint(Ab[r0*GP       + q*8 + tig]);
                af[i][1] = __float_as_uint(Ab[(r0+8)*GP   + q*8 + tig]);
                af[i][2] = __float_as_uint(Ab[r0*GP       + q*8 + tig + 4]);
                af[i][3] = __float_as_uint(Ab[(r0+8)*GP   + q*8 + tig + 4]);
            }
            #pragma unroll
            for (int j = 0; j < 4; j++) {
                int br = wn + j*8 + g;
                bf[j][0] = __float_as_uint(Bb[br*GP + q*8 + tig]);
                bf[j][1] = __float_as_uint(Bb[br*GP + q*8 + tig + 4]);
            }
            #pragma unroll
            for (int i = 0; i < 4; i++)
                #pragma unroll
                for (int j = 0; j < 4; j++)
                    mma_tf32(acc[i][j][0], acc[i][j][1], acc[i][j][2], acc[i][j][3],
                             af[i][0], af[i][1], af[i][2], af[i][3],
                             bf[j][0], bf[j][1]);
        }

        // ---- store prefetch into the other stage ----
        if (more) {
            float* Ad = As + (s ^ 1) * STAGE_F;
            float* Bd = Bs + (s ^ 1) * STAGE_F;
            #pragma unroll
            for (int j = 0; j < 4; j++) {
                uint32_t* d = (uint32_t*)&Ad[lr[j]*GP + lk[j]];
                d[0] = f2tf(pa[j].x); d[1] = f2tf(pa[j].y);
                d[2] = f2tf(pa[j].z); d[3] = f2tf(pa[j].w);
                uint32_t* e = (uint32_t*)&Bd[lr[j]*GP + lk[j]];
                e[0] = f2tf(pb[j].x); e[1] = f2tf(pb[j].y);
                e[2] = f2tf(pb[j].z); e[3] = f2tf(pb[j].w);
            }
        }
        __syncthreads();
    }

    // ---- epilogue ----
    #pragma unroll
    for (int i = 0; i < 4; i++) {
        #pragma unroll
        for (int j = 0; j < 4; j++) {
            int row = bm + wm + i*16 + g;
            int col = bn + wn + j*8 + 2*tig;
            if (col < N) {
                float v0 = acc[i][j][0], v1 = acc[i][j][1];
                float v2 = acc[i][j][2], v3 = acc[i][j][3];
                if (ACT == 1) {
                    float b0 = bias[col], b1 = bias[col+1];
                    v0 += b0; v1 += b1; v2 += b0; v3 += b1;
                    v0 = (v0 > 20.f) ? v0 : log1pf(__expf(v0));
                    v1 = (v1 > 20.f) ? v1 : log1pf(__expf(v1));
                    v2 = (v2 > 20.f) ? v2 : log1pf(__expf(v2));
                    v3 = (v3 > 20.f) ? v3 : log1pf(__expf(v3));
                }
                *(float2*)(C + (size_t)row * N + col)       = make_float2(v0, v1);
                *(float2*)(C + (size_t)(row + 8) * N + col) = make_float2(v2, v3);
            }
        }
    }
}

// ---------------- causal depthwise conv (width 4) + SiLU --------------------
__global__ __launch_bounds__(256) void conv_silu(
    const float* __restrict__ cw, const float* __restrict__ cb)
{
    int idx = blockIdx.x * 256 + threadIdx.x;
    int d4 = idx & (DIN/4 - 1);
    int t  = (idx >> 9) & (SEQ - 1);
    int b  = idx >> 19;
    int d  = d4 * 4;

    float wf[4][4];
    #pragma unroll
    for (int ch = 0; ch < 4; ch++) {
        float4 w = ((const float4*)cw)[d + ch];
        wf[ch][0] = w.x; wf[ch][1] = w.y; wf[ch][2] = w.z; wf[ch][3] = w.w;
    }
    float4 bias = ((const float4*)cb)[d4];
    float acc[4] = {bias.x, bias.y, bias.z, bias.w};

    #pragma unroll
    for (int j = 0; j < 4; j++) {
        int tt = t - 3 + j;
        if (tt >= 0) {
            const float4 xv = *(const float4*)&g_xz[((b*SEQ + tt) * (2*DIN)) + d];
            acc[0] = fmaf(xv.x, wf[0][j], acc[0]);
            acc[1] = fmaf(xv.y, wf[1][j], acc[1]);
            acc[2] = fmaf(xv.z, wf[2][j], acc[2]);
            acc[3] = fmaf(xv.w, wf[3][j], acc[3]);
        }
    }
    float4 out;
    out.x = acc[0] / (1.f + __expf(-acc[0]));
    out.y = acc[1] / (1.f + __expf(-acc[1]));
    out.z = acc[2] / (1.f + __expf(-acc[2]));
    out.w = acc[3] / (1.f + __expf(-acc[3]));
    *(float4*)&g_u[(b*SEQ + t) * DIN + d] = out;
}

// ---------------- selective scan: phase A -----------------------------------
__global__ __launch_bounds__(256) void scan_partA(const float* __restrict__ Alog)
{
    int d = blockIdx.x * 256 + threadIdx.x;
    int c = blockIdx.y;
    int b = blockIdx.z;

    float Arow[DSTATE];
    #pragma unroll
    for (int n = 0; n < DSTATE; n++) Arow[n] = -__expf(Alog[d*DSTATE + n]);

    float h[DSTATE], p[DSTATE];
    #pragma unroll
    for (int n = 0; n < DSTATE; n++) { h[n] = 0.f; p[n] = 1.f; }

    for (int i = 0; i < TCHUNK; i++) {
        int t = c * TCHUNK + i;
        int off = (b*SEQ + t) * DIN + d;
        float delta = g_delta[off];
        float u     = g_u[off];
        float du    = delta * u;
        const float4* Bp = (const float4*)(g_xdbl + (b*SEQ + t)*XDBL + DTRANK);
        float4 b0 = Bp[0], b1 = Bp[1], b2 = Bp[2], b3 = Bp[3];
        float Bv[DSTATE] = {b0.x,b0.y,b0.z,b0.w, b1.x,b1.y,b1.z,b1.w,
                            b2.x,b2.y,b2.z,b2.w, b3.x,b3.y,b3.z,b3.w};
        #pragma unroll
        for (int n = 0; n < DSTATE; n++) {
            float dA = __expf(delta * Arow[n]);
            p[n] *= dA;
            h[n] = fmaf(dA, h[n], du * Bv[n]);
        }
    }
    int o = ((b*NCHUNK + c) * DIN + d) * DSTATE;
    #pragma unroll
    for (int j = 0; j < 4; j++) {
        *(float4*)&g_P[o + j*4] = make_float4(p[j*4+0], p[j*4+1], p[j*4+2], p[j*4+3]);
        *(float4*)&g_q[o + j*4] = make_float4(h[j*4+0], h[j*4+1], h[j*4+2], h[j*4+3]);
    }
}

// ---------------- phase B ----------------------------------------------------
__global__ __launch_bounds__(256) void scan_partB()
{
    int idx = blockIdx.x * 256 + threadIdx.x;
    int b = idx >> 15;
    int rest = idx & 32767;
    float h = 0.f;
    for (int c = 0; c < NCHUNK; c++) {
        int o = (b*NCHUNK + c) * (DIN*DSTATE) + rest;
        g_hs[o] = h;
        h = fmaf(g_P[o], h, g_q[o]);
    }
}

// ---------------- phase C ----------------------------------------------------
__global__ __launch_bounds__(256) void scan_partC(
    const float* __restrict__ Alog, const float* __restrict__ Dv)
{
    int d = blockIdx.x * 256 + threadIdx.x;
    int c = blockIdx.y;
    int b = blockIdx.z;

    float Arow[DSTATE];
    #pragma unroll
    for (int n = 0; n < DSTATE; n++) Arow[n] = -__expf(Alog[d*DSTATE + n]);

    float h[DSTATE];
    {
        int o = ((b*NCHUNK + c) * DIN + d) * DSTATE;
        #pragma unroll
        for (int j = 0; j < 4; j++) {
            float4 v = *(const float4*)&g_hs[o + j*4];
            h[j*4+0] = v.x; h[j*4+1] = v.y; h[j*4+2] = v.z; h[j*4+3] = v.w;
        }
    }
    float Dd = Dv[d];

    for (int i = 0; i < TCHUNK; i++) {
        int t = c * TCHUNK + i;
        int off = (b*SEQ + t) * DIN + d;
        float delta = g_delta[off];
        float u     = g_u[off];
        float du    = delta * u;
        const float4* Bp = (const float4*)(g_xdbl + (b*SEQ + t)*XDBL + DTRANK);
        float4 b0 = Bp[0], b1 = Bp[1], b2 = Bp[2], b3 = Bp[3];
        float Bv[DSTATE] = {b0.x,b0.y,b0.z,b0.w, b1.x,b1.y,b1.z,b1.w,
                            b2.x,b2.y,b2.z,b2.w, b3.x,b3.y,b3.z,b3.w};
        const float4* Cp = (const float4*)(g_xdbl + (b*SEQ + t)*XDBL + DTRANK + DSTATE);
        float4 c0 = Cp[0], c1 = Cp[1], c2 = Cp[2], c3 = Cp[3];
        float Cv[DSTATE] = {c0.x,c0.y,c0.z,c0.w, c1.x,c1.y,c1.z,c1.w,
                            c2.x,c2.y,c2.z,c2.w, c3.x,c3.y,c3.z,c3.w};
        float y = 0.f;
        #pragma unroll
        for (int n = 0; n < DSTATE; n++) {
            float dA = __expf(delta * Arow[n]);
            h[n] = fmaf(dA, h[n], du * Bv[n]);
            y = fmaf(h[n], Cv[n], y);
        }
        float z = g_xz[(b*SEQ + t) * (2*DIN) + DIN + d];
        float gate = z / (1.f + __expf(-z));
        g_yg[off] = (y + u * Dd) * gate;
    }
}

// ---------------------------- launch -----------------------------------------
extern "C" void kernel_launch(void* const* d_in, const int* in_sizes, int n_in,
                              void* d_out, int out_size)
{
    const float* hs     = (const float*)d_in[0];
    const float* w_in   = (const float*)d_in[1];
    const float* conv_w = (const float*)d_in[2];
    const float* conv_b = (const float*)d_in[3];
    const float* w_x    = (const float*)d_in[4];
    const float* w_dt   = (const float*)d_in[5];
    const float* b_dt   = (const float*)d_in[6];
    const float* A_log  = (const float*)d_in[7];
    const float* Dv     = (const float*)d_in[8];
    const float* w_out  = (const float*)d_in[9];
    float* out = (float*)d_out;

    float *xz, *u, *xdbl, *delta, *yg;
    cudaGetSymbolAddress((void**)&xz,    g_xz);
    cudaGetSymbolAddress((void**)&u,     g_u);
    cudaGetSymbolAddress((void**)&xdbl,  g_xdbl);
    cudaGetSymbolAddress((void**)&delta, g_delta);
    cudaGetSymbolAddress((void**)&yg,    g_yg);

    cudaFuncSetAttribute(gemm_mma<2*DIN, DMODEL, 0>,
                         cudaFuncAttributeMaxDynamicSharedMemorySize, MMA_SMEM_BYTES);
    cudaFuncSetAttribute(gemm_mma<XDBL, DIN, 0>,
                         cudaFuncAttributeMaxDynamicSharedMemorySize, MMA_SMEM_BYTES);
    cudaFuncSetAttribute(gemm_mma<DIN, DTRANK, 1>,
                         cudaFuncAttributeMaxDynamicSharedMemorySize, MMA_SMEM_BYTES);
    cudaFuncSetAttribute(gemm_mma<DMODEL, DIN, 0>,
                         cudaFuncAttributeMaxDynamicSharedMemorySize, MMA_SMEM_BYTES);

    const int M = BATCH * SEQ;   // 2048

    // 1) xz = hs @ in_proj_w^T   [2048, 4096]
    {
        dim3 grid((2*DIN)/128, M/128);
        gemm_mma<2*DIN, DMODEL, 0><<<grid, 256, MMA_SMEM_BYTES>>>(hs, w_in, xz, nullptr);
    }
    // 2) u = silu(causal depthwise conv(x) + b)
    conv_silu<<<(BATCH*SEQ*(DIN/4))/256, 256>>>(conv_w, conv_b);

    // 3) x_dbl = u @ x_proj_w^T   [2048, 96]
    {
        dim3 grid(1, M/128);
        gemm_mma<XDBL, DIN, 0><<<grid, 256, MMA_SMEM_BYTES>>>(u, w_x, xdbl, nullptr);
    }
    // 4) delta = softplus(dt_low @ dt_proj_w^T + b)   [2048, 2048]
    {
        dim3 grid(DIN/128, M/128);
        gemm_mma<DIN, DTRANK, 1><<<grid, 256, MMA_SMEM_BYTES>>>(xdbl, w_dt, delta, b_dt);
    }
    // 5) selective scan (chunked, exact)
    {
        dim3 gridA(DIN/256, NCHUNK, BATCH);
        scan_partA<<<gridA, 256>>>(A_log);
        scan_partB<<<(BATCH*DIN*DSTATE)/256, 256>>>();
        scan_partC<<<gridA, 256>>>(A_log, Dv);
    }
    // 6) out = yg @ out_proj_w^T   [2048, 1024]
    {
        dim3 grid(DMODEL/128, M/128);
        gemm_mma<DMODEL, DIN, 0><<<grid, 256, MMA_SMEM_BYTES>>>(yg, w_out, out, nullptr);
    }
}